// round 11
// baseline (speedup 1.0000x reference)
#include <cuda_runtime.h>
#include <cuda_fp16.h>
#include <cstdint>
#include <math.h>

using ll = long long;

constexpr int B_ = 4, S_ = 2048, E_ = 2048, H_ = 16, D_ = 128;
constexpr int M_TOK = B_ * S_;        // 8192
constexpr int QKV_N = 3 * H_ * D_;    // 6144
constexpr int HD = H_ * D_;           // 2048
constexpr float RMS_EPS = 0.01f;
constexpr float SM_SCALE = 0.08838834764831845f;  // 1/sqrt(128)
constexpr float LOG2E = 1.4426950408889634f;

// ---------------- scratch (static device arrays; no cudaMalloc) ------------
__device__ __half g_xh[(size_t)M_TOK * E_];            // 32 MB
__device__ float  g_qkv[(size_t)M_TOK * QKV_N];        // 201 MB
__device__ __half g_wqkvT[(size_t)QKV_N * E_];         // 25 MB
__device__ __half g_wprojT[(size_t)E_ * E_];           // 8 MB
__device__ __half g_qh[(size_t)M_TOK * HD];            // 32 MB
__device__ __half g_kh[(size_t)M_TOK * HD];            // 32 MB
__device__ __half g_vT[(size_t)B_ * H_ * D_ * S_];     // 32 MB
__device__ __half g_attnh[(size_t)M_TOK * HD];         // 32 MB
__device__ float g_cos[S_ * 64];
__device__ float g_sin[S_ * 64];

// ---------------- helpers --------------------------------------------------
__device__ __forceinline__ uint32_t pack_h2(float lo, float hi) {
    uint32_t u;
    asm("cvt.rn.f16x2.f32 %0, %1, %2;" : "=r"(u) : "f"(hi), "f"(lo));
    return u;
}
__device__ __forceinline__ float ex2f(float x) {
    float y;
    asm("ex2.approx.ftz.f32 %0, %1;" : "=f"(y) : "f"(x));
    return y;
}
__device__ __forceinline__ uint32_t smem_u32(const void* p) {
    uint32_t a;
    asm("{ .reg .u64 t; cvta.to.shared.u64 t, %1; cvt.u32.u64 %0, t; }"
        : "=r"(a) : "l"(p));
    return a;
}
#define SWZ128(off) ((off) ^ (((off) >> 3) & 0x70))

#define MMA_F16(d, a, b)                                                     \
    asm volatile(                                                            \
        "mma.sync.aligned.m16n8k16.row.col.f32.f16.f16.f32 "                 \
        "{%0,%1,%2,%3}, {%4,%5,%6,%7}, {%8,%9}, {%0,%1,%2,%3};"              \
        : "+f"((d)[0]), "+f"((d)[1]), "+f"((d)[2]), "+f"((d)[3])             \
        : "r"((a)[0]), "r"((a)[1]), "r"((a)[2]), "r"((a)[3]),                \
          "r"((b)[0]), "r"((b)[1]))

// ---------------------------------------------------------------------------
__global__ void rope_table_kernel() {
    int idx = blockIdx.x * blockDim.x + threadIdx.x;
    if (idx >= S_ * 64) return;
    int s = idx >> 6, d = idx & 63;
    double f = pow(10000.0, -(double)d / 64.0);
    double ang = (double)s * f;
    g_cos[idx] = (float)cos(ang);
    g_sin[idx] = (float)sin(ang);
}

__global__ void half_copy(const float* __restrict__ in, __half* __restrict__ out,
                          int n4) {
    int i = blockIdx.x * blockDim.x + threadIdx.x;
    if (i >= n4) return;
    float4 v = ((const float4*)in)[i];
    uint2 o;
    o.x = pack_h2(v.x, v.y);
    o.y = pack_h2(v.z, v.w);
    ((uint2*)out)[i] = o;
}

// Batched transpose fp32 -> half: out[n][k] = half(in[k][n])
__global__ void transpose_half(const float* __restrict__ in, ll ldi, ll sIb, ll sIh,
                               __half* __restrict__ out, ll ldo, ll sOb, ll sOh) {
    __shared__ float t[32][33];
    const int z = blockIdx.z, zb = z >> 4, zh = z & 15;
    in += zb * sIb + zh * sIh;
    out += zb * sOb + zh * sOh;
    int k0 = blockIdx.y * 32, n0 = blockIdx.x * 32;
    int tx = threadIdx.x, ty = threadIdx.y;
#pragma unroll
    for (int i = 0; i < 4; i++)
        t[ty + i * 8][tx] = in[(ll)(k0 + ty + i * 8) * ldi + n0 + tx];
    __syncthreads();
#pragma unroll
    for (int i = 0; i < 4; i++)
        out[(ll)(n0 + ty + i * 8) * ldo + k0 + tx] =
            __float2half_rn(t[tx][ty + i * 8]);
}

// RMSNorm + RoPE (+ fold softmax scale into q); fp32 in, half out
__global__ void norm_rope_kernel(const float* __restrict__ qw,
                                 const float* __restrict__ kw) {
    int gw = blockIdx.x * 8 + (threadIdx.x >> 5);
    int lane = threadIdx.x & 31;
    int m = gw >> 5;
    int rem = gw & 31;
    int qk = rem >> 4;
    int h = rem & 15;
    const float* p = g_qkv + (size_t)m * QKV_N + qk * HD + h * D_;
    __half* o = (qk ? g_kh : g_qh) + (size_t)m * HD + h * D_;

    float x0 = p[lane], x1 = p[lane + 32], x2 = p[lane + 64], x3 = p[lane + 96];
    float ss = x0 * x0 + x1 * x1 + x2 * x2 + x3 * x3;
#pragma unroll
    for (int of = 16; of; of >>= 1) ss += __shfl_xor_sync(0xffffffffu, ss, of);
    float inv = rsqrtf(ss * (1.0f / 128.0f) + RMS_EPS);

    const float* w = qk ? kw : qw;
    float n0 = x0 * inv * w[lane];
    float n1 = x1 * inv * w[lane + 32];
    float n2 = x2 * inv * w[lane + 64];
    float n3 = x3 * inv * w[lane + 96];

    int s = m & (S_ - 1);
    float c0 = g_cos[s * 64 + lane],      sn0 = g_sin[s * 64 + lane];
    float c1 = g_cos[s * 64 + lane + 32], sn1 = g_sin[s * 64 + lane + 32];

    float o0 = n0 * c0 - n2 * sn0;
    float o1 = n1 * c1 - n3 * sn1;
    float o2 = n2 * c0 + n0 * sn0;
    float o3 = n3 * c1 + n1 * sn1;
    if (!qk) { o0 *= SM_SCALE; o1 *= SM_SCALE; o2 *= SM_SCALE; o3 *= SM_SCALE; }
    o[lane]      = __float2half_rn(o0);
    o[lane + 32] = __float2half_rn(o1);
    o[lane + 64] = __float2half_rn(o2);
    o[lane + 96] = __float2half_rn(o3);
}

// ---------------------------------------------------------------------------
// fp16 mma.sync GEMM (unchanged from R10): C[M,N] = A[M,K] * B[N,K]^T
// ---------------------------------------------------------------------------
constexpr int STAGE_BYTES = 32768;
constexpr int SMEM_GEMM = 3 * STAGE_BYTES;  // 96 KB

__global__ __launch_bounds__(256, 2) void gemm_h(
    const __half* __restrict__ A, ll lda,
    const __half* __restrict__ B, ll ldb,
    float* __restrict__ C, ll ldc, int K) {
    const int bx = blockIdx.x, by = blockIdx.y;
    const int m0 = by * 128, n0 = bx * 128;
    const int nT = K >> 6;

    extern __shared__ char smem[];
    const uint32_t base = smem_u32(smem);

    const int tid = threadIdx.x;
    const int warp = tid >> 5, lane = tid & 31;
    const int wm = warp >> 2, wn = warp & 3;

    const int c16 = (tid & 7) * 16;
    const int r0 = tid >> 3;

    auto load_stage = [&](int kt) {
        const int buf = kt % 3;
        const uint32_t sa = base + buf * STAGE_BYTES;
        const uint32_t sb = sa + 16384;
        const __half* Ap = A + kt * 64;
        const __half* Bp = B + kt * 64;
#pragma unroll
        for (int p = 0; p < 4; p++) {
            int r = r0 + p * 32;
            uint32_t off = SWZ128((uint32_t)(r * 128 + c16));
            const char* ga = (const char*)(Ap + (ll)(m0 + r) * lda) + c16;
            asm volatile("cp.async.cg.shared.global [%0], [%1], 16;"
                         :: "r"(sa + off), "l"(ga));
            const char* gb = (const char*)(Bp + (ll)(n0 + r) * ldb) + c16;
            asm volatile("cp.async.cg.shared.global [%0], [%1], 16;"
                         :: "r"(sb + off), "l"(gb));
        }
        asm volatile("cp.async.commit_group;" ::: "memory");
    };

    const int lq = lane & 7;
    const int aRowIn16 = lq + (((lane >> 3) & 1) << 3);
    const int aSel = lane >> 4;
    const int bSel = (lane >> 3) & 1;

    float acc[4][4][4];
#pragma unroll
    for (int i = 0; i < 4; i++)
#pragma unroll
        for (int j = 0; j < 4; j++)
#pragma unroll
            for (int r = 0; r < 4; r++) acc[i][j][r] = 0.0f;

    load_stage(0);
    load_stage(1);

    for (int kt = 0; kt < nT; kt++) {
        asm volatile("cp.async.wait_group 1;" ::: "memory");
        __syncthreads();
        if (kt + 2 < nT) load_stage(kt + 2);
        else asm volatile("cp.async.commit_group;" ::: "memory");

        const int buf = kt % 3;
        const uint32_t sa = base + buf * STAGE_BYTES;
        const uint32_t sb = sa + 16384;
        const uint32_t aBase = sa + (uint32_t)(wm * 64 + aRowIn16) * 128;
        const uint32_t bBase = sb + (uint32_t)(wn * 32 + lq) * 128;

#pragma unroll
        for (int g = 0; g < 4; g++) {
            uint32_t af[4][4];
#pragma unroll
            for (int i = 0; i < 4; i++) {
                uint32_t addr = aBase + i * 16 * 128 +
                                16u * (uint32_t)(((g << 1) | aSel) ^ lq);
                asm volatile(
                    "ldmatrix.sync.aligned.m8n8.x4.shared.b16 {%0,%1,%2,%3}, [%4];"
                    : "=r"(af[i][0]), "=r"(af[i][1]), "=r"(af[i][2]), "=r"(af[i][3])
                    : "r"(addr));
            }
            uint32_t bf[4][2];
#pragma unroll
            for (int j = 0; j < 4; j++) {
                uint32_t addr = bBase + j * 8 * 128 +
                                16u * (uint32_t)(((g << 1) | bSel) ^ lq);
                asm volatile(
                    "ldmatrix.sync.aligned.m8n8.x2.shared.b16 {%0,%1}, [%2];"
                    : "=r"(bf[j][0]), "=r"(bf[j][1]) : "r"(addr));
            }
#pragma unroll
            for (int i = 0; i < 4; i++)
#pragma unroll
                for (int j = 0; j < 4; j++) MMA_F16(acc[i][j], af[i], bf[j]);
        }
    }

    float* Cw = C + (ll)(m0 + wm * 64) * ldc + n0 + wn * 32;
    const int erow = lane >> 2, ecol = (lane & 3) * 2;
#pragma unroll
    for (int i = 0; i < 4; i++)
#pragma unroll
        for (int j = 0; j < 4; j++) {
            float2 v0, v1;
            v0.x = acc[i][j][0]; v0.y = acc[i][j][1];
            v1.x = acc[i][j][2]; v1.y = acc[i][j][3];
            float* cp = Cw + (ll)(i * 16 + erow) * ldc + j * 8 + ecol;
            *(float2*)cp = v0;
            *(float2*)(cp + 8 * ldc) = v1;
        }
}

// ---------------------------------------------------------------------------
// Fused flash attention (causal), fp16, warp-pair kv-split.
// q-tile = 64 rows, 8 warps: rowg = warp>>1 (16 q-rows), colg = warp&1
// (64 kv-cols of each 128-kv block). Cross-pair softmax stats via smem;
// partial O halves summed at the end. Ring chunks (16KB each):
//   rr=0,1: K d-chunk rr   (128 kv rows x 64 d)
//   rr=2,3: V d-half rr-2  (64 d rows x 128 s, stored as 128 x 128B rows:
//           row' = d_local*2 + s_half)
// ---------------------------------------------------------------------------
constexpr int FA_SMEM = 16384 + 65536 + 1024;  // Q + ring + stats

__global__ __launch_bounds__(256) void fa_kernel(
    const __half* __restrict__ qh_, const __half* __restrict__ kh_,
    const __half* __restrict__ vT_, __half* __restrict__ attn_) {
    const int qi = 31 - (int)blockIdx.x;       // heavy tiles first (64-row units)
    const int bh = blockIdx.y, b = bh >> 4, h = bh & 15;
    const __half* Qb = qh_ + (ll)(b * S_ + qi * 64) * HD + h * D_;
    const __half* Kb = kh_ + (ll)b * S_ * HD + h * D_;
    const __half* Vb = vT_ + (ll)bh * D_ * S_;
    __half* Ob = attn_ + (ll)(b * S_ + qi * 64) * HD + h * D_;

    extern __shared__ char smem[];
    const uint32_t qs = smem_u32(smem);
    const uint32_t ring = qs + 16384;
    const uint32_t mxbuf = qs + 16384 + 65536;        // 8 warps * 16 floats
    const uint32_t rsbuf = mxbuf + 512;

    const int tid = threadIdx.x, warp = tid >> 5, lane = tid & 31;
    const int rowg = warp >> 1, colg = warp & 1;
    const int c16 = (tid & 7) * 16, r0 = tid >> 3;

    // Q tile: 64 rows x 2 d-chunks of 128B (one commit group)
#pragma unroll
    for (int c = 0; c < 2; c++) {
#pragma unroll
        for (int p = 0; p < 2; p++) {
            int r = r0 + p * 32;
            uint32_t off = SWZ128((uint32_t)(r * 128 + c16));
            const char* g = (const char*)(Qb + (ll)r * HD) + c * 128 + c16;
            asm volatile("cp.async.cg.shared.global [%0], [%1], 16;"
                         :: "r"(qs + c * 8192 + off), "l"(g));
        }
    }
    asm volatile("cp.async.commit_group;" ::: "memory");

    const int nkv = (qi >> 1) + 1;
    const int total = nkv * 4;
    auto issue = [&](int ci) {
        if (ci < total) {
            const int kt = ci >> 2, rr = ci & 3;
            const uint32_t sa = ring + (ci & 3) * 16384;
            if (rr < 2) {  // K d-chunk rr: rows = kv, 64 d halves
#pragma unroll
                for (int p = 0; p < 4; p++) {
                    int r = r0 + p * 32;
                    uint32_t off = SWZ128((uint32_t)(r * 128 + c16));
                    const char* g =
                        (const char*)(Kb + (ll)(kt * 128 + r) * HD) + rr * 128 + c16;
                    asm volatile("cp.async.cg.shared.global [%0], [%1], 16;"
                                 :: "r"(sa + off), "l"(g));
                }
            } else {       // V d-half (rr-2): row' = d_local*2 + s_half
#pragma unroll
                for (int p = 0; p < 4; p++) {
                    int r = r0 + p * 32;   // row' 0..127
                    uint32_t off = SWZ128((uint32_t)(r * 128 + c16));
                    int d = (rr - 2) * 64 + (r >> 1);
                    const char* g = (const char*)(Vb + (ll)d * S_ + kt * 128 +
                                                  (r & 1) * 64) + c16;
                    asm volatile("cp.async.cg.shared.global [%0], [%1], 16;"
                                 :: "r"(sa + off), "l"(g));
                }
            }
        }
        asm volatile("cp.async.commit_group;" ::: "memory");
    };
    issue(0); issue(1); issue(2);

    const int lq = lane & 7;
    const int aRowIn16 = lq + (((lane >> 3) & 1) << 3);
    const int aSel = lane >> 4;
    const int bSel = (lane >> 3) & 1;
    const int q4 = lane & 3;
    const int qrow0 = qi * 64 + rowg * 16 + (lane >> 2);   // global q row

    float m0 = -1e30f, m1 = -1e30f, l0 = 0.0f, l1 = 0.0f;
    float accO[16][4];
#pragma unroll
    for (int j = 0; j < 16; j++)
#pragma unroll
        for (int r = 0; r < 4; r++) accO[j][r] = 0.0f;

    int ci = 0;
    for (int kt = 0; kt < nkv; kt++) {
        float accS[8][4];
#pragma unroll
        for (int j = 0; j < 8; j++)
#pragma unroll
            for (int r = 0; r < 4; r++) accS[j][r] = 0.0f;

        // ---- S = Q * K^T over 2 d-chunks; warp covers its 64 kv cols ----
#pragma unroll
        for (int c = 0; c < 2; c++) {
            asm volatile("cp.async.wait_group 2;" ::: "memory");
            __syncthreads();
            issue(ci + 3);
            const uint32_t sk = ring + (ci & 3) * 16384;
            const uint32_t aB = qs + c * 8192 + (uint32_t)(rowg * 16 + aRowIn16) * 128;
#pragma unroll
            for (int g = 0; g < 4; g++) {
                uint32_t af[4];
                uint32_t aaddr = aB + 16u * (uint32_t)(((g << 1) | aSel) ^ lq);
                asm volatile(
                    "ldmatrix.sync.aligned.m8n8.x4.shared.b16 {%0,%1,%2,%3}, [%4];"
                    : "=r"(af[0]), "=r"(af[1]), "=r"(af[2]), "=r"(af[3])
                    : "r"(aaddr));
#pragma unroll
                for (int j2 = 0; j2 < 8; j2++) {
                    uint32_t bf[2];
                    uint32_t baddr = sk +
                        (uint32_t)(colg * 64 + j2 * 8 + lq) * 128 +
                        16u * (uint32_t)(((g << 1) | bSel) ^ lq);
                    asm volatile(
                        "ldmatrix.sync.aligned.m8n8.x2.shared.b16 {%0,%1}, [%2];"
                        : "=r"(bf[0]), "=r"(bf[1]) : "r"(baddr));
                    MMA_F16(accS[j2], af, bf);
                }
            }
            ci++;
        }

        // ---- causal mask on last kv block -------------------------------
        if (kt == nkv - 1) {
            const int cbase = kt * 128 + colg * 64 + (q4 << 1);
#pragma unroll
            for (int j2 = 0; j2 < 8; j2++) {
                int col = cbase + j2 * 8;
                if (col     > qrow0)     accS[j2][0] = -1e30f;
                if (col + 1 > qrow0)     accS[j2][1] = -1e30f;
                if (col     > qrow0 + 8) accS[j2][2] = -1e30f;
                if (col + 1 > qrow0 + 8) accS[j2][3] = -1e30f;
            }
        }

        // ---- online softmax with cross-pair exchange --------------------
        float mx0 = -1e30f, mx1 = -1e30f;
#pragma unroll
        for (int j2 = 0; j2 < 8; j2++) {
            mx0 = fmaxf(mx0, fmaxf(accS[j2][0], accS[j2][1]));
            mx1 = fmaxf(mx1, fmaxf(accS[j2][2], accS[j2][3]));
        }
        mx0 = fmaxf(mx0, __shfl_xor_sync(0xffffffffu, mx0, 1));
        mx0 = fmaxf(mx0, __shfl_xor_sync(0xffffffffu, mx0, 2));
        mx1 = fmaxf(mx1, __shfl_xor_sync(0xffffffffu, mx1, 1));
        mx1 = fmaxf(mx1, __shfl_xor_sync(0xffffffffu, mx1, 2));
        if (q4 == 0) {
            *(float*)(smem + (mxbuf - qs) + (warp * 16 + (lane >> 2)) * 4) = mx0;
            *(float*)(smem + (mxbuf - qs) + (warp * 16 + 8 + (lane >> 2)) * 4) = mx1;
        }
        __syncthreads();
        {
            float pmx0 = *(const float*)(smem + (mxbuf - qs) +
                                         ((warp ^ 1) * 16 + (lane >> 2)) * 4);
            float pmx1 = *(const float*)(smem + (mxbuf - qs) +
                                         ((warp ^ 1) * 16 + 8 + (lane >> 2)) * 4);
            mx0 = fmaxf(mx0, pmx0);
            mx1 = fmaxf(mx1, pmx1);
        }
        const float mn0 = fmaxf(m0, mx0), mn1 = fmaxf(m1, mx1);
        const float sc0 = ex2f((m0 - mn0) * LOG2E);
        const float sc1 = ex2f((m1 - mn1) * LOG2E);
        float rs0 = 0.0f, rs1 = 0.0f;
        uint32_t ph0[8], ph1[8];
#pragma unroll
        for (int j2 = 0; j2 < 8; j2++) {
            float p0 = ex2f((accS[j2][0] - mn0) * LOG2E);
            float p1 = ex2f((accS[j2][1] - mn0) * LOG2E);
            float p2 = ex2f((accS[j2][2] - mn1) * LOG2E);
            float p3 = ex2f((accS[j2][3] - mn1) * LOG2E);
            rs0 += p0 + p1;
            rs1 += p2 + p3;
            ph0[j2] = pack_h2(p0, p1);
            ph1[j2] = pack_h2(p2, p3);
        }
        rs0 += __shfl_xor_sync(0xffffffffu, rs0, 1);
        rs0 += __shfl_xor_sync(0xffffffffu, rs0, 2);
        rs1 += __shfl_xor_sync(0xffffffffu, rs1, 1);
        rs1 += __shfl_xor_sync(0xffffffffu, rs1, 2);
        if (q4 == 0) {
            *(float*)(smem + (rsbuf - qs) + (warp * 16 + (lane >> 2)) * 4) = rs0;
            *(float*)(smem + (rsbuf - qs) + (warp * 16 + 8 + (lane >> 2)) * 4) = rs1;
        }
        __syncthreads();
        {
            float prs0 = *(const float*)(smem + (rsbuf - qs) +
                                         ((warp ^ 1) * 16 + (lane >> 2)) * 4);
            float prs1 = *(const float*)(smem + (rsbuf - qs) +
                                         ((warp ^ 1) * 16 + 8 + (lane >> 2)) * 4);
            rs0 += prs0;
            rs1 += prs1;
        }
        l0 = l0 * sc0 + rs0;
        l1 = l1 * sc1 + rs1;
#pragma unroll
        for (int j2 = 0; j2 < 16; j2++) {
            accO[j2][0] *= sc0; accO[j2][1] *= sc0;
            accO[j2][2] *= sc1; accO[j2][3] *= sc1;
        }
        m0 = mn0; m1 = mn1;

        // ---- accO += P * V over 2 V d-halves; k = warp's 64 kv ----------
#pragma unroll
        for (int vc = 0; vc < 2; vc++) {
            asm volatile("cp.async.wait_group 2;" ::: "memory");
            __syncthreads();
            issue(ci + 3);
            const uint32_t sv = ring + (ci & 3) * 16384;
#pragma unroll
            for (int gk = 0; gk < 4; gk++) {
                uint32_t af[4];
                af[0] = ph0[2 * gk];
                af[1] = ph1[2 * gk];
                af[2] = ph0[2 * gk + 1];
                af[3] = ph1[2 * gk + 1];
#pragma unroll
                for (int j2 = 0; j2 < 8; j2++) {
                    // row' = d_local*2 + colg ; d_local = j2*8 + lq
                    uint32_t rowp = (uint32_t)((j2 * 8 + lq) * 2 + colg);
                    uint32_t bf[2];
                    uint32_t baddr = sv + rowp * 128 +
                        16u * (uint32_t)(((gk << 1) | bSel) ^ (rowp & 7));
                    asm volatile(
                        "ldmatrix.sync.aligned.m8n8.x2.shared.b16 {%0,%1}, [%2];"
                        : "=r"(bf[0]), "=r"(bf[1]) : "r"(baddr));
                    MMA_F16(accO[vc * 8 + j2], af, bf);
                }
            }
            ci++;
        }
    }

    // ---- combine O halves across warp pairs (reuse ring smem) -----------
    __syncthreads();
    const uint32_t xb = ring + (uint32_t)rowg * 8192;
    if (colg == 1) {
#pragma unroll
        for (int j2 = 0; j2 < 16; j2++)
#pragma unroll
            for (int r = 0; r < 4; r++)
                *(float*)(smem + (xb - qs) + ((j2 * 4 + r) * 32 + lane) * 4) =
                    accO[j2][r];
    }
    __syncthreads();
    if (colg == 0) {
        const float inv0 = 1.0f / l0, inv1 = 1.0f / l1;
        const int rW = rowg * 16 + (lane >> 2);
        __half* o0 = Ob + (ll)rW * HD + (q4 << 1);
        __half* o1 = o0 + 8 * HD;
#pragma unroll
        for (int j2 = 0; j2 < 16; j2++) {
            float v0 = accO[j2][0] +
                *(const float*)(smem + (xb - qs) + ((j2 * 4 + 0) * 32 + lane) * 4);
            float v1 = accO[j2][1] +
                *(const float*)(smem + (xb - qs) + ((j2 * 4 + 1) * 32 + lane) * 4);
            float v2 = accO[j2][2] +
                *(const float*)(smem + (xb - qs) + ((j2 * 4 + 2) * 32 + lane) * 4);
            float v3 = accO[j2][3] +
                *(const float*)(smem + (xb - qs) + ((j2 * 4 + 3) * 32 + lane) * 4);
            *(uint32_t*)(o0 + j2 * 8) = pack_h2(v0 * inv0, v1 * inv0);
            *(uint32_t*)(o1 + j2 * 8) = pack_h2(v2 * inv1, v3 * inv1);
        }
    }
}

// ---------------------------------------------------------------------------
extern "C" void kernel_launch(void* const* d_in, const int* in_sizes, int n_in,
                              void* d_out, int out_size) {
    const float* x  = (const float*)d_in[0];
    const float* wq = (const float*)d_in[1];
    const float* wp = (const float*)d_in[2];
    const float* qw = (const float*)d_in[3];
    const float* kw = (const float*)d_in[4];
    float* y = (float*)d_out;

    __half *xh, *wqkvT, *wprojT, *qh, *kh, *vT, *attnh;
    float* qkv;
    cudaGetSymbolAddress((void**)&xh, g_xh);
    cudaGetSymbolAddress((void**)&qkv, g_qkv);
    cudaGetSymbolAddress((void**)&wqkvT, g_wqkvT);
    cudaGetSymbolAddress((void**)&wprojT, g_wprojT);
    cudaGetSymbolAddress((void**)&qh, g_qh);
    cudaGetSymbolAddress((void**)&kh, g_kh);
    cudaGetSymbolAddress((void**)&vT, g_vT);
    cudaGetSymbolAddress((void**)&attnh, g_attnh);

    cudaFuncSetAttribute(gemm_h,
                         cudaFuncAttributeMaxDynamicSharedMemorySize, SMEM_GEMM);
    cudaFuncSetAttribute(fa_kernel,
                         cudaFuncAttributeMaxDynamicSharedMemorySize, FA_SMEM);

    // launch index (ncu captures idx 3 = QKV GEMM):
    rope_table_kernel<<<(S_ * 64 + 255) / 256, 256>>>();
    half_copy<<<(M_TOK * E_ / 4 + 255) / 256, 256>>>(x, xh, M_TOK * E_ / 4);
    transpose_half<<<dim3(QKV_N / 32, E_ / 32, 1), dim3(32, 8)>>>(
        wq, QKV_N, 0, 0, wqkvT, E_, 0, 0);

    gemm_h<<<dim3(QKV_N / 128, M_TOK / 128), 256, SMEM_GEMM>>>(
        xh, E_, wqkvT, E_, qkv, QKV_N, E_);

    norm_rope_kernel<<<(2 * M_TOK * H_) / 8, 256>>>(qw, kw);

    transpose_half<<<dim3(E_ / 32, E_ / 32, 1), dim3(32, 8)>>>(
        wp, E_, 0, 0, wprojT, E_, 0, 0);

    // V: qkv fp32 [s][2HD + h*128 + d] -> vT half [bh][d][s]
    transpose_half<<<dim3(D_ / 32, S_ / 32, B_ * H_), dim3(32, 8)>>>(
        qkv + 2 * HD, QKV_N, (ll)S_ * QKV_N, 128,
        vT, S_, (ll)H_ * D_ * S_, (ll)D_ * S_);

    fa_kernel<<<dim3(32, 64), 256, FA_SMEM>>>(qh, kh, vT, attnh);

    gemm_h<<<dim3(E_ / 128, M_TOK / 128), 256, SMEM_GEMM>>>(
        attnh, HD, wprojT, E_, y, E_, E_);
}

// round 12
// speedup vs baseline: 1.1002x; 1.1002x over previous
#include <cuda_runtime.h>
#include <cuda_fp16.h>
#include <cstdint>
#include <math.h>

using ll = long long;

constexpr int B_ = 4, S_ = 2048, E_ = 2048, H_ = 16, D_ = 128;
constexpr int M_TOK = B_ * S_;        // 8192
constexpr int QKV_N = 3 * H_ * D_;    // 6144
constexpr int HD = H_ * D_;           // 2048
constexpr float RMS_EPS = 0.01f;
constexpr float SM_SCALE = 0.08838834764831845f;  // 1/sqrt(128)
constexpr float LOG2E = 1.4426950408889634f;

// ---------------- scratch (static device arrays; no cudaMalloc) ------------
__device__ __half g_xh[(size_t)M_TOK * E_];            // 32 MB
__device__ float  g_qkv[(size_t)M_TOK * QKV_N];        // 201 MB
__device__ __half g_wqkvT[(size_t)QKV_N * E_];         // 25 MB
__device__ __half g_wprojT[(size_t)E_ * E_];           // 8 MB
__device__ __half g_qh[(size_t)M_TOK * HD];            // 32 MB
__device__ __half g_kh[(size_t)M_TOK * HD];            // 32 MB
__device__ __half g_vT[(size_t)B_ * H_ * D_ * S_];     // 32 MB
__device__ __half g_attnh[(size_t)M_TOK * HD];         // 32 MB
__device__ float g_cos[S_ * 64];
__device__ float g_sin[S_ * 64];

// ---------------- helpers --------------------------------------------------
__device__ __forceinline__ uint32_t pack_h2(float lo, float hi) {
    uint32_t u;
    asm("cvt.rn.f16x2.f32 %0, %1, %2;" : "=r"(u) : "f"(hi), "f"(lo));
    return u;
}
__device__ __forceinline__ float ex2f(float x) {
    float y;
    asm("ex2.approx.ftz.f32 %0, %1;" : "=f"(y) : "f"(x));
    return y;
}
__device__ __forceinline__ uint32_t smem_u32(const void* p) {
    uint32_t a;
    asm("{ .reg .u64 t; cvta.to.shared.u64 t, %1; cvt.u32.u64 %0, t; }"
        : "=r"(a) : "l"(p));
    return a;
}
#define SWZ128(off) ((off) ^ (((off) >> 3) & 0x70))

#define MMA_F16(d, a, b)                                                     \
    asm volatile(                                                            \
        "mma.sync.aligned.m16n8k16.row.col.f32.f16.f16.f32 "                 \
        "{%0,%1,%2,%3}, {%4,%5,%6,%7}, {%8,%9}, {%0,%1,%2,%3};"              \
        : "+f"((d)[0]), "+f"((d)[1]), "+f"((d)[2]), "+f"((d)[3])             \
        : "r"((a)[0]), "r"((a)[1]), "r"((a)[2]), "r"((a)[3]),                \
          "r"((b)[0]), "r"((b)[1]))

// ---------------------------------------------------------------------------
__global__ void rope_table_kernel() {
    int idx = blockIdx.x * blockDim.x + threadIdx.x;
    if (idx >= S_ * 64) return;
    int s = idx >> 6, d = idx & 63;
    double f = pow(10000.0, -(double)d / 64.0);
    double ang = (double)s * f;
    g_cos[idx] = (float)cos(ang);
    g_sin[idx] = (float)sin(ang);
}

__global__ void half_copy(const float* __restrict__ in, __half* __restrict__ out,
                          int n4) {
    int i = blockIdx.x * blockDim.x + threadIdx.x;
    if (i >= n4) return;
    float4 v = ((const float4*)in)[i];
    uint2 o;
    o.x = pack_h2(v.x, v.y);
    o.y = pack_h2(v.z, v.w);
    ((uint2*)out)[i] = o;
}

// Batched transpose fp32 -> half: out[n][k] = half(in[k][n])
__global__ void transpose_half(const float* __restrict__ in, ll ldi, ll sIb, ll sIh,
                               __half* __restrict__ out, ll ldo, ll sOb, ll sOh) {
    __shared__ float t[32][33];
    const int z = blockIdx.z, zb = z >> 4, zh = z & 15;
    in += zb * sIb + zh * sIh;
    out += zb * sOb + zh * sOh;
    int k0 = blockIdx.y * 32, n0 = blockIdx.x * 32;
    int tx = threadIdx.x, ty = threadIdx.y;
#pragma unroll
    for (int i = 0; i < 4; i++)
        t[ty + i * 8][tx] = in[(ll)(k0 + ty + i * 8) * ldi + n0 + tx];
    __syncthreads();
#pragma unroll
    for (int i = 0; i < 4; i++)
        out[(ll)(n0 + ty + i * 8) * ldo + k0 + tx] =
            __float2half_rn(t[tx][ty + i * 8]);
}

// RMSNorm + RoPE (+ fold softmax scale into q); fp32 in, half out
__global__ void norm_rope_kernel(const float* __restrict__ qw,
                                 const float* __restrict__ kw) {
    int gw = blockIdx.x * 8 + (threadIdx.x >> 5);
    int lane = threadIdx.x & 31;
    int m = gw >> 5;
    int rem = gw & 31;
    int qk = rem >> 4;
    int h = rem & 15;
    const float* p = g_qkv + (size_t)m * QKV_N + qk * HD + h * D_;
    __half* o = (qk ? g_kh : g_qh) + (size_t)m * HD + h * D_;

    float x0 = p[lane], x1 = p[lane + 32], x2 = p[lane + 64], x3 = p[lane + 96];
    float ss = x0 * x0 + x1 * x1 + x2 * x2 + x3 * x3;
#pragma unroll
    for (int of = 16; of; of >>= 1) ss += __shfl_xor_sync(0xffffffffu, ss, of);
    float inv = rsqrtf(ss * (1.0f / 128.0f) + RMS_EPS);

    const float* w = qk ? kw : qw;
    float n0 = x0 * inv * w[lane];
    float n1 = x1 * inv * w[lane + 32];
    float n2 = x2 * inv * w[lane + 64];
    float n3 = x3 * inv * w[lane + 96];

    int s = m & (S_ - 1);
    float c0 = g_cos[s * 64 + lane],      sn0 = g_sin[s * 64 + lane];
    float c1 = g_cos[s * 64 + lane + 32], sn1 = g_sin[s * 64 + lane + 32];

    float o0 = n0 * c0 - n2 * sn0;
    float o1 = n1 * c1 - n3 * sn1;
    float o2 = n2 * c0 + n0 * sn0;
    float o3 = n3 * c1 + n1 * sn1;
    if (!qk) { o0 *= SM_SCALE; o1 *= SM_SCALE; o2 *= SM_SCALE; o3 *= SM_SCALE; }
    o[lane]      = __float2half_rn(o0);
    o[lane + 32] = __float2half_rn(o1);
    o[lane + 64] = __float2half_rn(o2);
    o[lane + 96] = __float2half_rn(o3);
}

// ---------------------------------------------------------------------------
// fp16 mma.sync GEMM: C[M,N] = A[M,K] * B[N,K]^T (half, K-major; C fp32).
// 128x128 CTA tile, BK=64, 3-stage cp.async, 128 threads (4 warps, 2x2 grid
// of 64x64 warp tiles -> 0.061 B/MAC crossbar load), 2 CTAs/SM.
// ---------------------------------------------------------------------------
constexpr int STAGE_BYTES = 32768;
constexpr int SMEM_GEMM = 3 * STAGE_BYTES;  // 96 KB

__global__ __launch_bounds__(128, 2) void gemm_h(
    const __half* __restrict__ A, ll lda,
    const __half* __restrict__ B, ll ldb,
    float* __restrict__ C, ll ldc, int K) {
    const int bx = blockIdx.x, by = blockIdx.y;
    const int m0 = by * 128, n0 = bx * 128;
    const int nT = K >> 6;

    extern __shared__ char smem[];
    const uint32_t base = smem_u32(smem);

    const int tid = threadIdx.x;
    const int warp = tid >> 5, lane = tid & 31;
    const int wm = warp >> 1, wn = warp & 1;

    const int c16 = (tid & 7) * 16;
    const int r0 = tid >> 3;          // 0..15

    auto load_stage = [&](int kt) {
        const int buf = kt % 3;
        const uint32_t sa = base + buf * STAGE_BYTES;
        const uint32_t sb = sa + 16384;
        const __half* Ap = A + kt * 64;
        const __half* Bp = B + kt * 64;
#pragma unroll
        for (int p = 0; p < 8; p++) {
            int r = r0 + p * 16;
            uint32_t off = SWZ128((uint32_t)(r * 128 + c16));
            const char* ga = (const char*)(Ap + (ll)(m0 + r) * lda) + c16;
            asm volatile("cp.async.cg.shared.global [%0], [%1], 16;"
                         :: "r"(sa + off), "l"(ga));
            const char* gb = (const char*)(Bp + (ll)(n0 + r) * ldb) + c16;
            asm volatile("cp.async.cg.shared.global [%0], [%1], 16;"
                         :: "r"(sb + off), "l"(gb));
        }
        asm volatile("cp.async.commit_group;" ::: "memory");
    };

    const int lq = lane & 7;
    const int aRowIn16 = lq + (((lane >> 3) & 1) << 3);
    const int aSel = lane >> 4;
    const int bSel = (lane >> 3) & 1;

    float acc[4][8][4];
#pragma unroll
    for (int i = 0; i < 4; i++)
#pragma unroll
        for (int j = 0; j < 8; j++)
#pragma unroll
            for (int r = 0; r < 4; r++) acc[i][j][r] = 0.0f;

    load_stage(0);
    load_stage(1);

    for (int kt = 0; kt < nT; kt++) {
        asm volatile("cp.async.wait_group 1;" ::: "memory");
        __syncthreads();
        if (kt + 2 < nT) load_stage(kt + 2);
        else asm volatile("cp.async.commit_group;" ::: "memory");

        const int buf = kt % 3;
        const uint32_t sa = base + buf * STAGE_BYTES;
        const uint32_t sb = sa + 16384;
        const uint32_t aBase = sa + (uint32_t)(wm * 64 + aRowIn16) * 128;
        const uint32_t bBase = sb + (uint32_t)(wn * 64 + lq) * 128;

#pragma unroll
        for (int g = 0; g < 4; g++) {
            uint32_t af[4][4];
#pragma unroll
            for (int i = 0; i < 4; i++) {
                uint32_t addr = aBase + i * 16 * 128 +
                                16u * (uint32_t)(((g << 1) | aSel) ^ lq);
                asm volatile(
                    "ldmatrix.sync.aligned.m8n8.x4.shared.b16 {%0,%1,%2,%3}, [%4];"
                    : "=r"(af[i][0]), "=r"(af[i][1]), "=r"(af[i][2]), "=r"(af[i][3])
                    : "r"(addr));
            }
            uint32_t bf[8][2];
#pragma unroll
            for (int j = 0; j < 8; j++) {
                uint32_t addr = bBase + j * 8 * 128 +
                                16u * (uint32_t)(((g << 1) | bSel) ^ lq);
                asm volatile(
                    "ldmatrix.sync.aligned.m8n8.x2.shared.b16 {%0,%1}, [%2];"
                    : "=r"(bf[j][0]), "=r"(bf[j][1]) : "r"(addr));
            }
#pragma unroll
            for (int i = 0; i < 4; i++)
#pragma unroll
                for (int j = 0; j < 8; j++) MMA_F16(acc[i][j], af[i], bf[j]);
        }
    }

    float* Cw = C + (ll)(m0 + wm * 64) * ldc + n0 + wn * 64;
    const int erow = lane >> 2, ecol = (lane & 3) * 2;
#pragma unroll
    for (int i = 0; i < 4; i++)
#pragma unroll
        for (int j = 0; j < 8; j++) {
            float2 v0, v1;
            v0.x = acc[i][j][0]; v0.y = acc[i][j][1];
            v1.x = acc[i][j][2]; v1.y = acc[i][j][3];
            float* cp = Cw + (ll)(i * 16 + erow) * ldc + j * 8 + ecol;
            *(float2*)cp = v0;
            *(float2*)(cp + 8 * ldc) = v1;
        }
}

// ---------------------------------------------------------------------------
// Fused flash attention (causal), fp16 — exact R10 form (best measured).
// Per CTA one (128-row q-tile, b, h); 8 warps x 16 q-rows.
// ---------------------------------------------------------------------------
constexpr int FA_SMEM = 32768 + 65536;  // Q + 4-stage ring

__global__ __launch_bounds__(256) void fa_kernel(
    const __half* __restrict__ qh_, const __half* __restrict__ kh_,
    const __half* __restrict__ vT_, __half* __restrict__ attn_) {
    const int qi = 15 - (int)blockIdx.x;       // heavy tiles first
    const int bh = blockIdx.y, b = bh >> 4, h = bh & 15;
    const __half* Qb = qh_ + (ll)(b * S_ + qi * 128) * HD + h * D_;
    const __half* Kb = kh_ + (ll)b * S_ * HD + h * D_;
    const __half* Vb = vT_ + (ll)bh * D_ * S_;
    __half* Ob = attn_ + (ll)(b * S_ + qi * 128) * HD + h * D_;

    extern __shared__ char smem[];
    const uint32_t qs = smem_u32(smem);
    const uint32_t ring = qs + 32768;

    const int tid = threadIdx.x, warp = tid >> 5, lane = tid & 31;
    const int c16 = (tid & 7) * 16, r0 = tid >> 3;

    // Q tile: 2 d-chunks of 128 rows x 128B
#pragma unroll
    for (int c = 0; c < 2; c++) {
#pragma unroll
        for (int p = 0; p < 4; p++) {
            int r = r0 + p * 32;
            uint32_t off = SWZ128((uint32_t)(r * 128 + c16));
            const char* g = (const char*)(Qb + (ll)r * HD) + c * 128 + c16;
            asm volatile("cp.async.cg.shared.global [%0], [%1], 16;"
                         :: "r"(qs + c * 16384 + off), "l"(g));
        }
    }
    asm volatile("cp.async.commit_group;" ::: "memory");

    const int total = (qi + 1) * 4;
    auto issue = [&](int ci) {
        if (ci < total) {
            const int kt = ci >> 2, rr = ci & 3;
            const uint32_t sa = ring + (ci & 3) * 16384;
            if (rr < 2) {  // K d-chunk rr
#pragma unroll
                for (int p = 0; p < 4; p++) {
                    int r = r0 + p * 32;
                    uint32_t off = SWZ128((uint32_t)(r * 128 + c16));
                    const char* g =
                        (const char*)(Kb + (ll)(kt * 128 + r) * HD) + rr * 128 + c16;
                    asm volatile("cp.async.cg.shared.global [%0], [%1], 16;"
                                 :: "r"(sa + off), "l"(g));
                }
            } else {       // V s-chunk rr-2 (rows = d)
#pragma unroll
                for (int p = 0; p < 4; p++) {
                    int r = r0 + p * 32;
                    uint32_t off = SWZ128((uint32_t)(r * 128 + c16));
                    const char* g = (const char*)(Vb + (ll)r * S_) + kt * 256 +
                                    (rr - 2) * 128 + c16;
                    asm volatile("cp.async.cg.shared.global [%0], [%1], 16;"
                                 :: "r"(sa + off), "l"(g));
                }
            }
        }
        asm volatile("cp.async.commit_group;" ::: "memory");
    };
    issue(0); issue(1); issue(2);

    const int lq = lane & 7;
    const int aRowIn16 = lq + (((lane >> 3) & 1) << 3);
    const int aSel = lane >> 4;
    const int bSel = (lane >> 3) & 1;
    const int q4 = lane & 3;

    float m0 = -1e30f, m1 = -1e30f, l0 = 0.0f, l1 = 0.0f;
    float accO[16][4];
#pragma unroll
    for (int j = 0; j < 16; j++)
#pragma unroll
        for (int r = 0; r < 4; r++) accO[j][r] = 0.0f;

    int ci = 0;
    for (int kt = 0; kt <= qi; kt++) {
        float accS[16][4];
#pragma unroll
        for (int j = 0; j < 16; j++)
#pragma unroll
            for (int r = 0; r < 4; r++) accS[j][r] = 0.0f;

        // ---- S = Q * K^T over 2 d-chunks --------------------------------
#pragma unroll
        for (int c = 0; c < 2; c++) {
            asm volatile("cp.async.wait_group 2;" ::: "memory");
            __syncthreads();
            issue(ci + 3);
            const uint32_t sk = ring + (ci & 3) * 16384;
            const uint32_t aB = qs + c * 16384 + (uint32_t)(warp * 16 + aRowIn16) * 128;
#pragma unroll
            for (int g = 0; g < 4; g++) {
                uint32_t af[4];
                uint32_t aaddr = aB + 16u * (uint32_t)(((g << 1) | aSel) ^ lq);
                asm volatile(
                    "ldmatrix.sync.aligned.m8n8.x4.shared.b16 {%0,%1,%2,%3}, [%4];"
                    : "=r"(af[0]), "=r"(af[1]), "=r"(af[2]), "=r"(af[3])
                    : "r"(aaddr));
#pragma unroll
                for (int j2 = 0; j2 < 16; j2++) {
                    uint32_t bf[2];
                    uint32_t baddr = sk + (uint32_t)(j2 * 8 + lq) * 128 +
                                     16u * (uint32_t)(((g << 1) | bSel) ^ lq);
                    asm volatile(
                        "ldmatrix.sync.aligned.m8n8.x2.shared.b16 {%0,%1}, [%2];"
                        : "=r"(bf[0]), "=r"(bf[1]) : "r"(baddr));
                    MMA_F16(accS[j2], af, bf);
                }
            }
            ci++;
        }

        // ---- causal mask on diagonal tile -------------------------------
        const int rW = warp * 16 + (lane >> 2);
        if (kt == qi) {
#pragma unroll
            for (int j2 = 0; j2 < 16; j2++) {
                int col = j2 * 8 + (q4 << 1);
                if (col     > rW)     accS[j2][0] = -1e30f;
                if (col + 1 > rW)     accS[j2][1] = -1e30f;
                if (col     > rW + 8) accS[j2][2] = -1e30f;
                if (col + 1 > rW + 8) accS[j2][3] = -1e30f;
            }
        }

        // ---- online softmax; P -> fp16 A-fragments (lane-local) ---------
        float mx0 = -1e30f, mx1 = -1e30f;
#pragma unroll
        for (int j2 = 0; j2 < 16; j2++) {
            mx0 = fmaxf(mx0, fmaxf(accS[j2][0], accS[j2][1]));
            mx1 = fmaxf(mx1, fmaxf(accS[j2][2], accS[j2][3]));
        }
        mx0 = fmaxf(mx0, __shfl_xor_sync(0xffffffffu, mx0, 1));
        mx0 = fmaxf(mx0, __shfl_xor_sync(0xffffffffu, mx0, 2));
        mx1 = fmaxf(mx1, __shfl_xor_sync(0xffffffffu, mx1, 1));
        mx1 = fmaxf(mx1, __shfl_xor_sync(0xffffffffu, mx1, 2));
        const float mn0 = fmaxf(m0, mx0), mn1 = fmaxf(m1, mx1);
        const float sc0 = ex2f((m0 - mn0) * LOG2E);
        const float sc1 = ex2f((m1 - mn1) * LOG2E);
        float rs0 = 0.0f, rs1 = 0.0f;
        uint32_t ph0[16], ph1[16];
#pragma unroll
        for (int j2 = 0; j2 < 16; j2++) {
            float p0 = ex2f((accS[j2][0] - mn0) * LOG2E);
            float p1 = ex2f((accS[j2][1] - mn0) * LOG2E);
            float p2 = ex2f((accS[j2][2] - mn1) * LOG2E);
            float p3 = ex2f((accS[j2][3] - mn1) * LOG2E);
            rs0 += p0 + p1;
            rs1 += p2 + p3;
            ph0[j2] = pack_h2(p0, p1);   // rows m      (a0/a2 source)
            ph1[j2] = pack_h2(p2, p3);   // rows m+8    (a1/a3 source)
        }
        rs0 += __shfl_xor_sync(0xffffffffu, rs0, 1);
        rs0 += __shfl_xor_sync(0xffffffffu, rs0, 2);
        rs1 += __shfl_xor_sync(0xffffffffu, rs1, 1);
        rs1 += __shfl_xor_sync(0xffffffffu, rs1, 2);
        l0 = l0 * sc0 + rs0;
        l1 = l1 * sc1 + rs1;
#pragma unroll
        for (int j2 = 0; j2 < 16; j2++) {
            accO[j2][0] *= sc0; accO[j2][1] *= sc0;
            accO[j2][2] *= sc1; accO[j2][3] *= sc1;
        }
        m0 = mn0; m1 = mn1;

        // ---- accO += P * V over 2 s-chunks ------------------------------
#pragma unroll
        for (int sc = 0; sc < 2; sc++) {
            asm volatile("cp.async.wait_group 2;" ::: "memory");
            __syncthreads();
            issue(ci + 3);
            const uint32_t sv = ring + (ci & 3) * 16384;
#pragma unroll
            for (int g = 0; g < 4; g++) {
                const int gk = sc * 4 + g;
                uint32_t af[4];
                af[0] = ph0[2 * gk];
                af[1] = ph1[2 * gk];
                af[2] = ph0[2 * gk + 1];
                af[3] = ph1[2 * gk + 1];
#pragma unroll
                for (int j2 = 0; j2 < 16; j2++) {
                    uint32_t bf[2];
                    uint32_t baddr = sv + (uint32_t)(j2 * 8 + lq) * 128 +
                                     16u * (uint32_t)(((g << 1) | bSel) ^ lq);
                    asm volatile(
                        "ldmatrix.sync.aligned.m8n8.x2.shared.b16 {%0,%1}, [%2];"
                        : "=r"(bf[0]), "=r"(bf[1]) : "r"(baddr));
                    MMA_F16(accO[j2], af, bf);
                }
            }
            ci++;
        }
    }

    // ---- normalize + store (half) ----------------------------------------
    const float inv0 = 1.0f / l0, inv1 = 1.0f / l1;
    const int rW = warp * 16 + (lane >> 2);
    __half* o0 = Ob + (ll)rW * HD + (q4 << 1);
    __half* o1 = o0 + 8 * HD;
#pragma unroll
    for (int j2 = 0; j2 < 16; j2++) {
        *(uint32_t*)(o0 + j2 * 8) = pack_h2(accO[j2][0] * inv0, accO[j2][1] * inv0);
        *(uint32_t*)(o1 + j2 * 8) = pack_h2(accO[j2][2] * inv1, accO[j2][3] * inv1);
    }
}

// ---------------------------------------------------------------------------
extern "C" void kernel_launch(void* const* d_in, const int* in_sizes, int n_in,
                              void* d_out, int out_size) {
    const float* x  = (const float*)d_in[0];
    const float* wq = (const float*)d_in[1];
    const float* wp = (const float*)d_in[2];
    const float* qw = (const float*)d_in[3];
    const float* kw = (const float*)d_in[4];
    float* y = (float*)d_out;

    __half *xh, *wqkvT, *wprojT, *qh, *kh, *vT, *attnh;
    float* qkv;
    cudaGetSymbolAddress((void**)&xh, g_xh);
    cudaGetSymbolAddress((void**)&qkv, g_qkv);
    cudaGetSymbolAddress((void**)&wqkvT, g_wqkvT);
    cudaGetSymbolAddress((void**)&wprojT, g_wprojT);
    cudaGetSymbolAddress((void**)&qh, g_qh);
    cudaGetSymbolAddress((void**)&kh, g_kh);
    cudaGetSymbolAddress((void**)&vT, g_vT);
    cudaGetSymbolAddress((void**)&attnh, g_attnh);

    cudaFuncSetAttribute(gemm_h,
                         cudaFuncAttributeMaxDynamicSharedMemorySize, SMEM_GEMM);
    cudaFuncSetAttribute(fa_kernel,
                         cudaFuncAttributeMaxDynamicSharedMemorySize, FA_SMEM);

    // launch index (ncu captures idx 3 = QKV GEMM):
    rope_table_kernel<<<(S_ * 64 + 255) / 256, 256>>>();
    half_copy<<<(M_TOK * E_ / 4 + 255) / 256, 256>>>(x, xh, M_TOK * E_ / 4);
    transpose_half<<<dim3(QKV_N / 32, E_ / 32, 1), dim3(32, 8)>>>(
        wq, QKV_N, 0, 0, wqkvT, E_, 0, 0);

    gemm_h<<<dim3(QKV_N / 128, M_TOK / 128), 128, SMEM_GEMM>>>(
        xh, E_, wqkvT, E_, qkv, QKV_N, E_);

    norm_rope_kernel<<<(2 * M_TOK * H_) / 8, 256>>>(qw, kw);

    transpose_half<<<dim3(E_ / 32, E_ / 32, 1), dim3(32, 8)>>>(
        wp, E_, 0, 0, wprojT, E_, 0, 0);

    // V: qkv fp32 [s][2HD + h*128 + d] -> vT half [bh][d][s]
    transpose_half<<<dim3(D_ / 32, S_ / 32, B_ * H_), dim3(32, 8)>>>(
        qkv + 2 * HD, QKV_N, (ll)S_ * QKV_N, 128,
        vT, S_, (ll)H_ * D_ * S_, (ll)D_ * S_);

    fa_kernel<<<dim3(16, 64), 256, FA_SMEM>>>(qh, kh, vT, attnh);

    gemm_h<<<dim3(E_ / 128, M_TOK / 128), 128, SMEM_GEMM>>>(
        attnh, HD, wprojT, E_, y, E_, E_);
}

// round 13
// speedup vs baseline: 1.1480x; 1.0435x over previous
#include <cuda_runtime.h>
#include <cuda_fp16.h>
#include <cstdint>
#include <math.h>

using ll = long long;

constexpr int B_ = 4, S_ = 2048, E_ = 2048, H_ = 16, D_ = 128;
constexpr int M_TOK = B_ * S_;        // 8192
constexpr int QKV_N = 3 * H_ * D_;    // 6144
constexpr int HD = H_ * D_;           // 2048
constexpr float RMS_EPS = 0.01f;
constexpr float SM_SCALE = 0.08838834764831845f;  // 1/sqrt(128)
constexpr float LOG2E = 1.4426950408889634f;

// ---------------- scratch (static device arrays; no cudaMalloc) ------------
__device__ __half g_xh[(size_t)M_TOK * E_];            // 32 MB
__device__ float  g_qkv[(size_t)M_TOK * QKV_N];        // 201 MB
__device__ __half g_wqkvT[(size_t)QKV_N * E_];         // 25 MB
__device__ __half g_wprojT[(size_t)E_ * E_];           // 8 MB
__device__ __half g_qh[(size_t)M_TOK * HD];            // 32 MB
__device__ __half g_kh[(size_t)M_TOK * HD];            // 32 MB
__device__ __half g_vT[(size_t)B_ * H_ * D_ * S_];     // 32 MB
__device__ __half g_attnh[(size_t)M_TOK * HD];         // 32 MB
__device__ float g_cos[S_ * 64];
__device__ float g_sin[S_ * 64];

// ---------------- helpers --------------------------------------------------
__device__ __forceinline__ uint32_t pack_h2(float lo, float hi) {
    uint32_t u;
    asm("cvt.rn.f16x2.f32 %0, %1, %2;" : "=r"(u) : "f"(hi), "f"(lo));
    return u;
}
__device__ __forceinline__ float ex2f(float x) {
    float y;
    asm("ex2.approx.ftz.f32 %0, %1;" : "=f"(y) : "f"(x));
    return y;
}
__device__ __forceinline__ uint32_t smem_u32(const void* p) {
    uint32_t a;
    asm("{ .reg .u64 t; cvta.to.shared.u64 t, %1; cvt.u32.u64 %0, t; }"
        : "=r"(a) : "l"(p));
    return a;
}
#define SWZ128(off) ((off) ^ (((off) >> 3) & 0x70))

#define MMA_F16(d, a, b)                                                     \
    asm volatile(                                                            \
        "mma.sync.aligned.m16n8k16.row.col.f32.f16.f16.f32 "                 \
        "{%0,%1,%2,%3}, {%4,%5,%6,%7}, {%8,%9}, {%0,%1,%2,%3};"              \
        : "+f"((d)[0]), "+f"((d)[1]), "+f"((d)[2]), "+f"((d)[3])             \
        : "r"((a)[0]), "r"((a)[1]), "r"((a)[2]), "r"((a)[3]),                \
          "r"((b)[0]), "r"((b)[1]))

// ---------------------------------------------------------------------------
__global__ void rope_table_kernel() {
    int idx = blockIdx.x * blockDim.x + threadIdx.x;
    if (idx >= S_ * 64) return;
    int s = idx >> 6, d = idx & 63;
    double f = pow(10000.0, -(double)d / 64.0);
    double ang = (double)s * f;
    g_cos[idx] = (float)cos(ang);
    g_sin[idx] = (float)sin(ang);
}

__global__ void half_copy(const float* __restrict__ in, __half* __restrict__ out,
                          int n4) {
    int i = blockIdx.x * blockDim.x + threadIdx.x;
    if (i >= n4) return;
    float4 v = ((const float4*)in)[i];
    uint2 o;
    o.x = pack_h2(v.x, v.y);
    o.y = pack_h2(v.z, v.w);
    ((uint2*)out)[i] = o;
}

// Batched transpose fp32 -> half: out[n][k] = half(in[k][n])
__global__ void transpose_half(const float* __restrict__ in, ll ldi, ll sIb, ll sIh,
                               __half* __restrict__ out, ll ldo, ll sOb, ll sOh) {
    __shared__ float t[32][33];
    const int z = blockIdx.z, zb = z >> 4, zh = z & 15;
    in += zb * sIb + zh * sIh;
    out += zb * sOb + zh * sOh;
    int k0 = blockIdx.y * 32, n0 = blockIdx.x * 32;
    int tx = threadIdx.x, ty = threadIdx.y;
#pragma unroll
    for (int i = 0; i < 4; i++)
        t[ty + i * 8][tx] = in[(ll)(k0 + ty + i * 8) * ldi + n0 + tx];
    __syncthreads();
#pragma unroll
    for (int i = 0; i < 4; i++)
        out[(ll)(n0 + ty + i * 8) * ldo + k0 + tx] =
            __float2half_rn(t[tx][ty + i * 8]);
}

// RMSNorm + RoPE (+ fold softmax scale into q); fp32 in, half out
__global__ void norm_rope_kernel(const float* __restrict__ qw,
                                 const float* __restrict__ kw) {
    int gw = blockIdx.x * 8 + (threadIdx.x >> 5);
    int lane = threadIdx.x & 31;
    int m = gw >> 5;
    int rem = gw & 31;
    int qk = rem >> 4;
    int h = rem & 15;
    const float* p = g_qkv + (size_t)m * QKV_N + qk * HD + h * D_;
    __half* o = (qk ? g_kh : g_qh) + (size_t)m * HD + h * D_;

    float x0 = p[lane], x1 = p[lane + 32], x2 = p[lane + 64], x3 = p[lane + 96];
    float ss = x0 * x0 + x1 * x1 + x2 * x2 + x3 * x3;
#pragma unroll
    for (int of = 16; of; of >>= 1) ss += __shfl_xor_sync(0xffffffffu, ss, of);
    float inv = rsqrtf(ss * (1.0f / 128.0f) + RMS_EPS);

    const float* w = qk ? kw : qw;
    float n0 = x0 * inv * w[lane];
    float n1 = x1 * inv * w[lane + 32];
    float n2 = x2 * inv * w[lane + 64];
    float n3 = x3 * inv * w[lane + 96];

    int s = m & (S_ - 1);
    float c0 = g_cos[s * 64 + lane],      sn0 = g_sin[s * 64 + lane];
    float c1 = g_cos[s * 64 + lane + 32], sn1 = g_sin[s * 64 + lane + 32];

    float o0 = n0 * c0 - n2 * sn0;
    float o1 = n1 * c1 - n3 * sn1;
    float o2 = n2 * c0 + n0 * sn0;
    float o3 = n3 * c1 + n1 * sn1;
    if (!qk) { o0 *= SM_SCALE; o1 *= SM_SCALE; o2 *= SM_SCALE; o3 *= SM_SCALE; }
    o[lane]      = __float2half_rn(o0);
    o[lane + 32] = __float2half_rn(o1);
    o[lane + 64] = __float2half_rn(o2);
    o[lane + 96] = __float2half_rn(o3);
}

// ---------------------------------------------------------------------------
// fp16 mma.sync GEMM (unchanged from R12 WIN): 128x128 CTA, 4 warps of 64x64.
// ---------------------------------------------------------------------------
constexpr int STAGE_BYTES = 32768;
constexpr int SMEM_GEMM = 3 * STAGE_BYTES;  // 96 KB

__global__ __launch_bounds__(128, 2) void gemm_h(
    const __half* __restrict__ A, ll lda,
    const __half* __restrict__ B, ll ldb,
    float* __restrict__ C, ll ldc, int K) {
    const int bx = blockIdx.x, by = blockIdx.y;
    const int m0 = by * 128, n0 = bx * 128;
    const int nT = K >> 6;

    extern __shared__ char smem[];
    const uint32_t base = smem_u32(smem);

    const int tid = threadIdx.x;
    const int warp = tid >> 5, lane = tid & 31;
    const int wm = warp >> 1, wn = warp & 1;

    const int c16 = (tid & 7) * 16;
    const int r0 = tid >> 3;          // 0..15

    auto load_stage = [&](int kt) {
        const int buf = kt % 3;
        const uint32_t sa = base + buf * STAGE_BYTES;
        const uint32_t sb = sa + 16384;
        const __half* Ap = A + kt * 64;
        const __half* Bp = B + kt * 64;
#pragma unroll
        for (int p = 0; p < 8; p++) {
            int r = r0 + p * 16;
            uint32_t off = SWZ128((uint32_t)(r * 128 + c16));
            const char* ga = (const char*)(Ap + (ll)(m0 + r) * lda) + c16;
            asm volatile("cp.async.cg.shared.global [%0], [%1], 16;"
                         :: "r"(sa + off), "l"(ga));
            const char* gb = (const char*)(Bp + (ll)(n0 + r) * ldb) + c16;
            asm volatile("cp.async.cg.shared.global [%0], [%1], 16;"
                         :: "r"(sb + off), "l"(gb));
        }
        asm volatile("cp.async.commit_group;" ::: "memory");
    };

    const int lq = lane & 7;
    const int aRowIn16 = lq + (((lane >> 3) & 1) << 3);
    const int aSel = lane >> 4;
    const int bSel = (lane >> 3) & 1;

    float acc[4][8][4];
#pragma unroll
    for (int i = 0; i < 4; i++)
#pragma unroll
        for (int j = 0; j < 8; j++)
#pragma unroll
            for (int r = 0; r < 4; r++) acc[i][j][r] = 0.0f;

    load_stage(0);
    load_stage(1);

    for (int kt = 0; kt < nT; kt++) {
        asm volatile("cp.async.wait_group 1;" ::: "memory");
        __syncthreads();
        if (kt + 2 < nT) load_stage(kt + 2);
        else asm volatile("cp.async.commit_group;" ::: "memory");

        const int buf = kt % 3;
        const uint32_t sa = base + buf * STAGE_BYTES;
        const uint32_t sb = sa + 16384;
        const uint32_t aBase = sa + (uint32_t)(wm * 64 + aRowIn16) * 128;
        const uint32_t bBase = sb + (uint32_t)(wn * 64 + lq) * 128;

#pragma unroll
        for (int g = 0; g < 4; g++) {
            uint32_t af[4][4];
#pragma unroll
            for (int i = 0; i < 4; i++) {
                uint32_t addr = aBase + i * 16 * 128 +
                                16u * (uint32_t)(((g << 1) | aSel) ^ lq);
                asm volatile(
                    "ldmatrix.sync.aligned.m8n8.x4.shared.b16 {%0,%1,%2,%3}, [%4];"
                    : "=r"(af[i][0]), "=r"(af[i][1]), "=r"(af[i][2]), "=r"(af[i][3])
                    : "r"(addr));
            }
            uint32_t bf[8][2];
#pragma unroll
            for (int j = 0; j < 8; j++) {
                uint32_t addr = bBase + j * 8 * 128 +
                                16u * (uint32_t)(((g << 1) | bSel) ^ lq);
                asm volatile(
                    "ldmatrix.sync.aligned.m8n8.x2.shared.b16 {%0,%1}, [%2];"
                    : "=r"(bf[j][0]), "=r"(bf[j][1]) : "r"(addr));
            }
#pragma unroll
            for (int i = 0; i < 4; i++)
#pragma unroll
                for (int j = 0; j < 8; j++) MMA_F16(acc[i][j], af[i], bf[j]);
        }
    }

    float* Cw = C + (ll)(m0 + wm * 64) * ldc + n0 + wn * 64;
    const int erow = lane >> 2, ecol = (lane & 3) * 2;
#pragma unroll
    for (int i = 0; i < 4; i++)
#pragma unroll
        for (int j = 0; j < 8; j++) {
            float2 v0, v1;
            v0.x = acc[i][j][0]; v0.y = acc[i][j][1];
            v1.x = acc[i][j][2]; v1.y = acc[i][j][3];
            float* cp = Cw + (ll)(i * 16 + erow) * ldc + j * 8 + ecol;
            *(float2*)cp = v0;
            *(float2*)(cp + 8 * ldc) = v1;
        }
}

// ---------------------------------------------------------------------------
// Fused flash attention (causal), fp16, fat warp tiles.
// q-tile 128, 8 warps: rowg = warp&3 (32 q-rows), colg = (warp>>2)&1
// (64 kv-cols of each 128 block; SMSP-balanced). Each B fragment feeds 2 mmas.
// Cross-pair softmax stats via 1KB smem exchange; O k-halves combined at end
// through the drained ring smem. Streaming skeleton identical to R10.
// ---------------------------------------------------------------------------
constexpr int FA_SMEM = 32768 + 65536 + 2048;  // Q + ring + stat bufs

__global__ __launch_bounds__(256) void fa_kernel(
    const __half* __restrict__ qh_, const __half* __restrict__ kh_,
    const __half* __restrict__ vT_, __half* __restrict__ attn_) {
    const int qi = 15 - (int)blockIdx.x;       // heavy tiles first
    const int bh = blockIdx.y, b = bh >> 4, h = bh & 15;
    const __half* Qb = qh_ + (ll)(b * S_ + qi * 128) * HD + h * D_;
    const __half* Kb = kh_ + (ll)b * S_ * HD + h * D_;
    const __half* Vb = vT_ + (ll)bh * D_ * S_;
    __half* Ob = attn_ + (ll)(b * S_ + qi * 128) * HD + h * D_;

    extern __shared__ char smem[];
    const uint32_t qs = smem_u32(smem);
    const uint32_t ring = qs + 32768;
    float* mxbuf = (float*)(smem + 32768 + 65536);        // 256 floats
    float* rsbuf = mxbuf + 256;

    const int tid = threadIdx.x, warp = tid >> 5, lane = tid & 31;
    const int rowg = warp & 3, colg = (warp >> 2) & 1;
    const int c16 = (tid & 7) * 16, r0 = tid >> 3;

    // Q tile: 2 d-chunks of 128 rows x 128B
#pragma unroll
    for (int c = 0; c < 2; c++) {
#pragma unroll
        for (int p = 0; p < 4; p++) {
            int r = r0 + p * 32;
            uint32_t off = SWZ128((uint32_t)(r * 128 + c16));
            const char* g = (const char*)(Qb + (ll)r * HD) + c * 128 + c16;
            asm volatile("cp.async.cg.shared.global [%0], [%1], 16;"
                         :: "r"(qs + c * 16384 + off), "l"(g));
        }
    }
    asm volatile("cp.async.commit_group;" ::: "memory");

    const int total = (qi + 1) * 4;
    auto issue = [&](int ci) {
        if (ci < total) {
            const int kt = ci >> 2, rr = ci & 3;
            const uint32_t sa = ring + (ci & 3) * 16384;
            if (rr < 2) {  // K d-chunk rr
#pragma unroll
                for (int p = 0; p < 4; p++) {
                    int r = r0 + p * 32;
                    uint32_t off = SWZ128((uint32_t)(r * 128 + c16));
                    const char* g =
                        (const char*)(Kb + (ll)(kt * 128 + r) * HD) + rr * 128 + c16;
                    asm volatile("cp.async.cg.shared.global [%0], [%1], 16;"
                                 :: "r"(sa + off), "l"(g));
                }
            } else {       // V s-chunk rr-2 (rows = d)
#pragma unroll
                for (int p = 0; p < 4; p++) {
                    int r = r0 + p * 32;
                    uint32_t off = SWZ128((uint32_t)(r * 128 + c16));
                    const char* g = (const char*)(Vb + (ll)r * S_) + kt * 256 +
                                    (rr - 2) * 128 + c16;
                    asm volatile("cp.async.cg.shared.global [%0], [%1], 16;"
                                 :: "r"(sa + off), "l"(g));
                }
            }
        }
        asm volatile("cp.async.commit_group;" ::: "memory");
    };
    issue(0); issue(1); issue(2);

    const int lq = lane & 7;
    const int aRowIn16 = lq + (((lane >> 3) & 1) << 3);
    const int aSel = lane >> 4;
    const int bSel = (lane >> 3) & 1;
    const int q4 = lane & 3;
    const int lrow = lane >> 2;                  // 0..7

    float mS[2][2], lS[2][2];
#pragma unroll
    for (int i = 0; i < 2; i++) {
        mS[i][0] = -1e30f; mS[i][1] = -1e30f;
        lS[i][0] = 0.0f;   lS[i][1] = 0.0f;
    }
    float accO[2][16][4];
#pragma unroll
    for (int i = 0; i < 2; i++)
#pragma unroll
        for (int j = 0; j < 16; j++)
#pragma unroll
            for (int r = 0; r < 4; r++) accO[i][j][r] = 0.0f;

    int ci = 0;
    for (int kt = 0; kt <= qi; kt++) {
        float accS[2][8][4];
#pragma unroll
        for (int i = 0; i < 2; i++)
#pragma unroll
            for (int j = 0; j < 8; j++)
#pragma unroll
                for (int r = 0; r < 4; r++) accS[i][j][r] = 0.0f;

        // ---- S = Q * K^T over 2 d-chunks; warp: 32 q x 64 kv ------------
#pragma unroll
        for (int c = 0; c < 2; c++) {
            asm volatile("cp.async.wait_group 2;" ::: "memory");
            __syncthreads();
            issue(ci + 3);
            const uint32_t sk = ring + (ci & 3) * 16384;
            const uint32_t aB = qs + c * 16384 +
                                (uint32_t)(rowg * 32 + aRowIn16) * 128;
#pragma unroll
            for (int g = 0; g < 4; g++) {
                uint32_t af[2][4];
#pragma unroll
                for (int i = 0; i < 2; i++) {
                    uint32_t aaddr = aB + i * 16 * 128 +
                                     16u * (uint32_t)(((g << 1) | aSel) ^ lq);
                    asm volatile(
                        "ldmatrix.sync.aligned.m8n8.x4.shared.b16 {%0,%1,%2,%3}, [%4];"
                        : "=r"(af[i][0]), "=r"(af[i][1]),
                          "=r"(af[i][2]), "=r"(af[i][3])
                        : "r"(aaddr));
                }
#pragma unroll
                for (int j2 = 0; j2 < 8; j2++) {
                    uint32_t bf[2];
                    uint32_t baddr = sk +
                        (uint32_t)(colg * 64 + j2 * 8 + lq) * 128 +
                        16u * (uint32_t)(((g << 1) | bSel) ^ lq);
                    asm volatile(
                        "ldmatrix.sync.aligned.m8n8.x2.shared.b16 {%0,%1}, [%2];"
                        : "=r"(bf[0]), "=r"(bf[1]) : "r"(baddr));
                    MMA_F16(accS[0][j2], af[0], bf);
                    MMA_F16(accS[1][j2], af[1], bf);
                }
            }
            ci++;
        }

        // ---- causal mask on diagonal block ------------------------------
        if (kt == qi) {
            const int cb = colg * 64 + (q4 << 1);   // col rel to kv block
#pragma unroll
            for (int i = 0; i < 2; i++) {
                const int rb = rowg * 32 + i * 16 + lrow;  // row rel to q tile
#pragma unroll
                for (int j2 = 0; j2 < 8; j2++) {
                    int col = cb + j2 * 8;
                    if (col     > rb)     accS[i][j2][0] = -1e30f;
                    if (col + 1 > rb)     accS[i][j2][1] = -1e30f;
                    if (col     > rb + 8) accS[i][j2][2] = -1e30f;
                    if (col + 1 > rb + 8) accS[i][j2][3] = -1e30f;
                }
            }
        }

        // ---- online softmax with cross-pair (colg) exchange -------------
        float mx[2][2];
#pragma unroll
        for (int i = 0; i < 2; i++) {
            float a = -1e30f, b2 = -1e30f;
#pragma unroll
            for (int j2 = 0; j2 < 8; j2++) {
                a  = fmaxf(a,  fmaxf(accS[i][j2][0], accS[i][j2][1]));
                b2 = fmaxf(b2, fmaxf(accS[i][j2][2], accS[i][j2][3]));
            }
            a  = fmaxf(a,  __shfl_xor_sync(0xffffffffu, a, 1));
            a  = fmaxf(a,  __shfl_xor_sync(0xffffffffu, a, 2));
            b2 = fmaxf(b2, __shfl_xor_sync(0xffffffffu, b2, 1));
            b2 = fmaxf(b2, __shfl_xor_sync(0xffffffffu, b2, 2));
            mx[i][0] = a; mx[i][1] = b2;
        }
        if (q4 == 0) {
#pragma unroll
            for (int i = 0; i < 2; i++) {
                mxbuf[warp * 32 + i * 16 + lrow]     = mx[i][0];
                mxbuf[warp * 32 + i * 16 + 8 + lrow] = mx[i][1];
            }
        }
        __syncthreads();
#pragma unroll
        for (int i = 0; i < 2; i++) {
            mx[i][0] = fmaxf(mx[i][0], mxbuf[(warp ^ 4) * 32 + i * 16 + lrow]);
            mx[i][1] = fmaxf(mx[i][1], mxbuf[(warp ^ 4) * 32 + i * 16 + 8 + lrow]);
        }

        float sc[2][2], rs[2][2];
        uint32_t ph0[2][8], ph1[2][8];
#pragma unroll
        for (int i = 0; i < 2; i++) {
            const float mn0 = fmaxf(mS[i][0], mx[i][0]);
            const float mn1 = fmaxf(mS[i][1], mx[i][1]);
            sc[i][0] = ex2f((mS[i][0] - mn0) * LOG2E);
            sc[i][1] = ex2f((mS[i][1] - mn1) * LOG2E);
            float r0s = 0.0f, r1s = 0.0f;
#pragma unroll
            for (int j2 = 0; j2 < 8; j2++) {
                float p0 = ex2f((accS[i][j2][0] - mn0) * LOG2E);
                float p1 = ex2f((accS[i][j2][1] - mn0) * LOG2E);
                float p2 = ex2f((accS[i][j2][2] - mn1) * LOG2E);
                float p3 = ex2f((accS[i][j2][3] - mn1) * LOG2E);
                r0s += p0 + p1;
                r1s += p2 + p3;
                ph0[i][j2] = pack_h2(p0, p1);
                ph1[i][j2] = pack_h2(p2, p3);
            }
            r0s += __shfl_xor_sync(0xffffffffu, r0s, 1);
            r0s += __shfl_xor_sync(0xffffffffu, r0s, 2);
            r1s += __shfl_xor_sync(0xffffffffu, r1s, 1);
            r1s += __shfl_xor_sync(0xffffffffu, r1s, 2);
            rs[i][0] = r0s; rs[i][1] = r1s;
            mS[i][0] = mn0; mS[i][1] = mn1;
        }
        if (q4 == 0) {
#pragma unroll
            for (int i = 0; i < 2; i++) {
                rsbuf[warp * 32 + i * 16 + lrow]     = rs[i][0];
                rsbuf[warp * 32 + i * 16 + 8 + lrow] = rs[i][1];
            }
        }
        __syncthreads();
#pragma unroll
        for (int i = 0; i < 2; i++) {
            rs[i][0] += rsbuf[(warp ^ 4) * 32 + i * 16 + lrow];
            rs[i][1] += rsbuf[(warp ^ 4) * 32 + i * 16 + 8 + lrow];
            lS[i][0] = lS[i][0] * sc[i][0] + rs[i][0];
            lS[i][1] = lS[i][1] * sc[i][1] + rs[i][1];
#pragma unroll
            for (int j2 = 0; j2 < 16; j2++) {
                accO[i][j2][0] *= sc[i][0]; accO[i][j2][1] *= sc[i][0];
                accO[i][j2][2] *= sc[i][1]; accO[i][j2][3] *= sc[i][1];
            }
        }

        // ---- accO += P * V; warp computes only on its kv half -----------
#pragma unroll
        for (int vc = 0; vc < 2; vc++) {
            asm volatile("cp.async.wait_group 2;" ::: "memory");
            __syncthreads();
            issue(ci + 3);
            if (vc == colg) {
                const uint32_t sv = ring + (ci & 3) * 16384;
#pragma unroll
                for (int gk = 0; gk < 4; gk++) {
                    uint32_t af0[4], af1[4];
                    af0[0] = ph0[0][2 * gk];     af0[1] = ph1[0][2 * gk];
                    af0[2] = ph0[0][2 * gk + 1]; af0[3] = ph1[0][2 * gk + 1];
                    af1[0] = ph0[1][2 * gk];     af1[1] = ph1[1][2 * gk];
                    af1[2] = ph0[1][2 * gk + 1]; af1[3] = ph1[1][2 * gk + 1];
#pragma unroll
                    for (int j2 = 0; j2 < 16; j2++) {
                        uint32_t bf[2];
                        uint32_t baddr = sv + (uint32_t)(j2 * 8 + lq) * 128 +
                                         16u * (uint32_t)(((gk << 1) | bSel) ^ lq);
                        asm volatile(
                            "ldmatrix.sync.aligned.m8n8.x2.shared.b16 {%0,%1}, [%2];"
                            : "=r"(bf[0]), "=r"(bf[1]) : "r"(baddr));
                        MMA_F16(accO[0][j2], af0, bf);
                        MMA_F16(accO[1][j2], af1, bf);
                    }
                }
            }
            ci++;
        }
    }

    // ---- drain cp.async, combine O halves across colg, store ------------
    asm volatile("cp.async.wait_group 0;" ::: "memory");
    __syncthreads();
    float* xb = (float*)(smem + 32768) + rowg * 4096;   // 16KB per rowg
    if (colg == 1) {
#pragma unroll
        for (int i = 0; i < 2; i++)
#pragma unroll
            for (int j2 = 0; j2 < 16; j2++)
#pragma unroll
                for (int r = 0; r < 4; r++)
                    xb[((i * 16 + j2) * 4 + r) * 32 + lane] = accO[i][j2][r];
    }
    __syncthreads();
    if (colg == 0) {
#pragma unroll
        for (int i = 0; i < 2; i++) {
            const float inv0 = 1.0f / lS[i][0], inv1 = 1.0f / lS[i][1];
            const int rW = rowg * 32 + i * 16 + lrow;
            __half* o0 = Ob + (ll)rW * HD + (q4 << 1);
            __half* o1 = o0 + 8 * HD;
#pragma unroll
            for (int j2 = 0; j2 < 16; j2++) {
                float v0 = accO[i][j2][0] + xb[((i * 16 + j2) * 4 + 0) * 32 + lane];
                float v1 = accO[i][j2][1] + xb[((i * 16 + j2) * 4 + 1) * 32 + lane];
                float v2 = accO[i][j2][2] + xb[((i * 16 + j2) * 4 + 2) * 32 + lane];
                float v3 = accO[i][j2][3] + xb[((i * 16 + j2) * 4 + 3) * 32 + lane];
                *(uint32_t*)(o0 + j2 * 8) = pack_h2(v0 * inv0, v1 * inv0);
                *(uint32_t*)(o1 + j2 * 8) = pack_h2(v2 * inv1, v3 * inv1);
            }
        }
    }
}

// ---------------------------------------------------------------------------
extern "C" void kernel_launch(void* const* d_in, const int* in_sizes, int n_in,
                              void* d_out, int out_size) {
    const float* x  = (const float*)d_in[0];
    const float* wq = (const float*)d_in[1];
    const float* wp = (const float*)d_in[2];
    const float* qw = (const float*)d_in[3];
    const float* kw = (const float*)d_in[4];
    float* y = (float*)d_out;

    __half *xh, *wqkvT, *wprojT, *qh, *kh, *vT, *attnh;
    float* qkv;
    cudaGetSymbolAddress((void**)&xh, g_xh);
    cudaGetSymbolAddress((void**)&qkv, g_qkv);
    cudaGetSymbolAddress((void**)&wqkvT, g_wqkvT);
    cudaGetSymbolAddress((void**)&wprojT, g_wprojT);
    cudaGetSymbolAddress((void**)&qh, g_qh);
    cudaGetSymbolAddress((void**)&kh, g_kh);
    cudaGetSymbolAddress((void**)&vT, g_vT);
    cudaGetSymbolAddress((void**)&attnh, g_attnh);

    cudaFuncSetAttribute(gemm_h,
                         cudaFuncAttributeMaxDynamicSharedMemorySize, SMEM_GEMM);
    cudaFuncSetAttribute(fa_kernel,
                         cudaFuncAttributeMaxDynamicSharedMemorySize, FA_SMEM);

    // launch index (ncu captures idx 3 = QKV GEMM):
    rope_table_kernel<<<(S_ * 64 + 255) / 256, 256>>>();
    half_copy<<<(M_TOK * E_ / 4 + 255) / 256, 256>>>(x, xh, M_TOK * E_ / 4);
    transpose_half<<<dim3(QKV_N / 32, E_ / 32, 1), dim3(32, 8)>>>(
        wq, QKV_N, 0, 0, wqkvT, E_, 0, 0);

    gemm_h<<<dim3(QKV_N / 128, M_TOK / 128), 128, SMEM_GEMM>>>(
        xh, E_, wqkvT, E_, qkv, QKV_N, E_);

    norm_rope_kernel<<<(2 * M_TOK * H_) / 8, 256>>>(qw, kw);

    transpose_half<<<dim3(E_ / 32, E_ / 32, 1), dim3(32, 8)>>>(
        wp, E_, 0, 0, wprojT, E_, 0, 0);

    // V: qkv fp32 [s][2HD + h*128 + d] -> vT half [bh][d][s]
    transpose_half<<<dim3(D_ / 32, S_ / 32, B_ * H_), dim3(32, 8)>>>(
        qkv + 2 * HD, QKV_N, (ll)S_ * QKV_N, 128,
        vT, S_, (ll)H_ * D_ * S_, (ll)D_ * S_);

    fa_kernel<<<dim3(16, 64), 256, FA_SMEM>>>(qh, kh, vT, attnh);

    gemm_h<<<dim3(E_ / 128, M_TOK / 128), 128, SMEM_GEMM>>>(
        attnh, HD, wprojT, E_, y, E_, E_);
}